// round 5
// baseline (speedup 1.0000x reference)
#include <cuda_runtime.h>
#include <cuda_bf16.h>
#include <math_constants.h>
#include <cstdint>

// ---------------- Geometry ----------------
#define MDIM  5184          // 72*72
#define CDIM  256
#define MPAD  5248          // 41 * 128
#define NBLK  41
#define NTILES (NBLK * NBLK)
#define NK    8             // K chunks of 32 over CDIM
#define OUT_H 224
#define OUT_W 224

// smem stage: 4 operand tiles (Ah, Al, Bh, Bl), each 128 rows x 32 bf16, row stride 80 B
#define ROW_STRIDE 80
#define OP_BYTES   (128 * ROW_STRIDE)          // 10240
#define OFF_AH     0
#define OFF_AL     (1 * OP_BYTES)
#define OFF_BH     (2 * OP_BYTES)
#define OFF_BL     (3 * OP_BYTES)
#define STAGE      (4 * OP_BYTES)              // 40960
#define NSTAGE     4
#define DYN_SMEM   (NSTAGE * STAGE)            // 163840

// ---------------- Device scratch (allocation-free) ----------------
// Row-major [MPAD][512] bf16: cols [0,256)=hi, [256,512)=lo. 5.4 MB each.
__device__ __align__(16) __nv_bfloat16 g_A2[MPAD * 512];
__device__ __align__(16) __nv_bfloat16 g_B2[MPAD * 512];
__device__ float        g_rpos[MDIM], g_rneg[MDIM], g_cpos[MDIM], g_cneg[MDIM];
__device__ unsigned int g_maxkey;

// ---------------- PTX helpers (baseline sm_100: cp.async / ldmatrix / HMMA) ----------------
__device__ __forceinline__ uint32_t smem_u32(const void* p) {
    uint32_t a;
    asm("{ .reg .u64 t; cvta.to.shared.u64 t, %1; cvt.u32.u64 %0, t; }" : "=r"(a) : "l"(p));
    return a;
}
__device__ __forceinline__ unsigned int fkey(float f) {
    unsigned int u = __float_as_uint(f);
    return (u & 0x80000000u) ? ~u : (u | 0x80000000u);
}

#define CP16(dst, src) \
    asm volatile("cp.async.cg.shared.global [%0], [%1], 16;" :: "r"(dst), "l"(src))
#define CP_COMMIT()  asm volatile("cp.async.commit_group;")
#define CP_WAIT(n)   asm volatile("cp.async.wait_group %0;" :: "n"(n))

#define LDSM4(r0, r1, r2, r3, a) \
    asm volatile("ldmatrix.sync.aligned.m8n8.x4.shared.b16 {%0,%1,%2,%3}, [%4];" \
                 : "=r"(r0), "=r"(r1), "=r"(r2), "=r"(r3) : "r"(a))

#define MMA16816(d, a, b) \
    asm volatile("mma.sync.aligned.m16n8k16.row.col.f32.bf16.bf16.f32 " \
                 "{%0,%1,%2,%3}, {%4,%5,%6,%7}, {%8,%9}, {%0,%1,%2,%3};" \
                 : "+f"((d)[0]), "+f"((d)[1]), "+f"((d)[2]), "+f"((d)[3]) \
                 : "r"((a)[0]), "r"((a)[1]), "r"((a)[2]), "r"((a)[3]), \
                   "r"((b)[0]), "r"((b)[1]))

// ---------------- Kernels ----------------

// Fused prep: fp32 -> bf16 hi/lo split + zero reduction arrays + zero pad rows.
__global__ void simcam_conv(const float* __restrict__ x) {
    int id = blockIdx.x * blockDim.x + threadIdx.x;
    // Zero reduction arrays + maxkey + pad rows [5184,5248) of both operand arrays.
    if (id < MDIM) { g_rpos[id] = 0.f; g_rneg[id] = 0.f; g_cpos[id] = 0.f; g_cneg[id] = 0.f; }
    if (id == 0) g_maxkey = 0u;
    if (id < 8192) {   // 64 pad rows * 1024 B = 4096 uint4 per array
        const uint4 z = make_uint4(0u, 0u, 0u, 0u);
        __nv_bfloat16* base = (id < 4096) ? g_A2 : g_B2;
        ((uint4*)(base + (size_t)MDIM * 512))[id & 4095] = z;
    }
    if (id >= 2 * MDIM * 128) return;
    int op  = id >= MDIM * 128;
    int rid = op ? id - MDIM * 128 : id;
    int r   = rid >> 7;
    int k0  = (rid & 127) * 2;
    float2 v = *(const float2*)(x + ((size_t)op * MDIM + r) * CDIM + k0);
    __nv_bfloat16 h0 = __float2bfloat16(v.x);
    __nv_bfloat16 h1 = __float2bfloat16(v.y);
    __nv_bfloat16 l0 = __float2bfloat16(v.x - __bfloat162float(h0));
    __nv_bfloat16 l1 = __float2bfloat16(v.y - __bfloat162float(h1));
    unsigned int hpack = ((unsigned)__bfloat16_as_ushort(h1) << 16) | __bfloat16_as_ushort(h0);
    unsigned int lpack = ((unsigned)__bfloat16_as_ushort(l1) << 16) | __bfloat16_as_ushort(l0);
    __nv_bfloat16* base = op ? g_B2 : g_A2;
    *(unsigned int*)(base + (size_t)r * 512 + k0)       = hpack;
    *(unsigned int*)(base + (size_t)r * 512 + 256 + k0) = lpack;
}

__device__ __forceinline__ void load_stage(uint32_t sb, const unsigned char* Asrc,
                                           const unsigned char* Bsrc, int kc, int tid) {
    #pragma unroll
    for (int i = 0; i < 2; i++) {
        int idx = tid + i * 256;           // 0..511
        int row = idx >> 2;
        int ch  = idx & 3;
        uint32_t soff = (uint32_t)(row * ROW_STRIDE + ch * 16);
        size_t   goff = (size_t)row * 1024 + kc * 64 + ch * 16;
        CP16(sb + OFF_AH + soff, Asrc + goff);
        CP16(sb + OFF_AL + soff, Asrc + goff + 512);
        CP16(sb + OFF_BH + soff, Bsrc + goff);
        CP16(sb + OFF_BL + soff, Bsrc + goff + 512);
    }
}

// Persistent fused GEMM: C = Ah*Bh^T + Al*Bh^T + Ah*Bl^T per 128x128 tile,
// + relu row/col sums + global max. One wave of 148 CTAs loops over all tiles.
__global__ __launch_bounds__(256, 1) void simcam_gemm() {
    extern __shared__ unsigned char dsm[];
    __shared__ float s_rp[128], s_rn[128], s_cp[128], s_cn[128], s_wmax[8];

    const int tid  = threadIdx.x;
    const int wid  = tid >> 5, lane = tid & 31;
    const int wm   = wid & 3, wn = wid >> 2;     // 4x2 warp grid; warp tile 32(M) x 64(N)
    const uint32_t dyn = smem_u32(dsm);

    // ldmatrix per-lane address components (4 mats: rows(l&15), chunk(l>>4))
    const uint32_t a_off = (uint32_t)((wm * 32 + (lane & 15)) * ROW_STRIDE + (lane >> 4) * 16);
    const uint32_t b_off = (uint32_t)((wn * 64 + (lane & 15)) * ROW_STRIDE + (lane >> 4) * 16);

    for (int tile = blockIdx.x; tile < NTILES; tile += gridDim.x) {
        const int bm = tile / NBLK, bn = tile % NBLK;
        const unsigned char* Asrc = (const unsigned char*)(g_A2 + (size_t)bm * 128 * 512);
        const unsigned char* Bsrc = (const unsigned char*)(g_B2 + (size_t)bn * 128 * 512);

        if (tid < 128) { s_rp[tid] = 0.f; s_rn[tid] = 0.f; s_cp[tid] = 0.f; s_cn[tid] = 0.f; }

        float acc[2][8][4];
        #pragma unroll
        for (int mi = 0; mi < 2; mi++)
            #pragma unroll
            for (int nf = 0; nf < 8; nf++)
                #pragma unroll
                for (int r = 0; r < 4; r++) acc[mi][nf][r] = 0.f;

        // Pipeline prologue: 3 stages in flight.
        #pragma unroll
        for (int p = 0; p < 3; p++) {
            load_stage(dyn + p * STAGE, Asrc, Bsrc, p, tid);
            CP_COMMIT();
        }

        #pragma unroll 1
        for (int kc = 0; kc < NK; kc++) {
            // Wait for stage kc: pending-group bound depends on how many were issued.
            if      (kc <= 5) CP_WAIT(2);
            else if (kc == 6) CP_WAIT(1);
            else              CP_WAIT(0);
            __syncthreads();
            if (kc + 3 < NK) {
                load_stage(dyn + ((kc + 3) & 3) * STAGE, Asrc, Bsrc, kc + 3, tid);
                CP_COMMIT();
            }

            const uint32_t base = dyn + (kc & 3) * STAGE;
            #pragma unroll
            for (int s = 0; s < 2; s++) {
                uint32_t ah[2][4], al[2][4], bb[8][2];
                #pragma unroll
                for (int mi = 0; mi < 2; mi++)
                    LDSM4(ah[mi][0], ah[mi][1], ah[mi][2], ah[mi][3],
                          base + OFF_AH + a_off + mi * (16 * ROW_STRIDE) + s * 32);
                #pragma unroll
                for (int g = 0; g < 4; g++) {
                    uint32_t r0, r1, r2, r3;
                    LDSM4(r0, r1, r2, r3, base + OFF_BH + b_off + g * (16 * ROW_STRIDE) + s * 32);
                    bb[2 * g][0] = r0; bb[2 * g][1] = r2;
                    bb[2 * g + 1][0] = r1; bb[2 * g + 1][1] = r3;
                }
                #pragma unroll
                for (int mi = 0; mi < 2; mi++)
                    #pragma unroll
                    for (int nf = 0; nf < 8; nf++) MMA16816(acc[mi][nf], ah[mi], bb[nf]);
                #pragma unroll
                for (int mi = 0; mi < 2; mi++)
                    LDSM4(al[mi][0], al[mi][1], al[mi][2], al[mi][3],
                          base + OFF_AL + a_off + mi * (16 * ROW_STRIDE) + s * 32);
                #pragma unroll
                for (int mi = 0; mi < 2; mi++)
                    #pragma unroll
                    for (int nf = 0; nf < 8; nf++) MMA16816(acc[mi][nf], al[mi], bb[nf]);
                #pragma unroll
                for (int g = 0; g < 4; g++) {
                    uint32_t r0, r1, r2, r3;
                    LDSM4(r0, r1, r2, r3, base + OFF_BL + b_off + g * (16 * ROW_STRIDE) + s * 32);
                    bb[2 * g][0] = r0; bb[2 * g][1] = r2;
                    bb[2 * g + 1][0] = r1; bb[2 * g + 1][1] = r3;
                }
                #pragma unroll
                for (int mi = 0; mi < 2; mi++)
                    #pragma unroll
                    for (int nf = 0; nf < 8; nf++) MMA16816(acc[mi][nf], ah[mi], bb[nf]);
            }
        }
        __syncthreads();   // all stages consumed; s_* zeroed and ready

        // ---- Fused epilogue ----
        // rows = wm*32 + mi*16 + (lane>>2) + {0,8}; cols = wn*64 + nf*8 + (lane&3)*2 + {0,1}
        float tmax = -CUDART_INF_F;
        const int rbase = bm * 128 + wm * 32;
        const int cbase = bn * 128 + wn * 64;

        #pragma unroll
        for (int mi = 0; mi < 2; mi++) {
            #pragma unroll
            for (int h = 0; h < 2; h++) {
                float rp = 0.f, rn = 0.f;
                #pragma unroll
                for (int nf = 0; nf < 8; nf++) {
                    float v0 = acc[mi][nf][2 * h], v1 = acc[mi][nf][2 * h + 1];
                    rp += fmaxf(v0, 0.f) + fmaxf(v1, 0.f);
                    rn += fmaxf(-v0, 0.f) + fmaxf(-v1, 0.f);
                    int grow = rbase + mi * 16 + (lane >> 2) + h * 8;
                    int gc0  = cbase + nf * 8 + (lane & 3) * 2;
                    if (grow < MDIM && gc0 < MDIM)     tmax = fmaxf(tmax, v0);
                    if (grow < MDIM && gc0 + 1 < MDIM) tmax = fmaxf(tmax, v1);
                }
                rp += __shfl_xor_sync(0xffffffffu, rp, 1); rp += __shfl_xor_sync(0xffffffffu, rp, 2);
                rn += __shfl_xor_sync(0xffffffffu, rn, 1); rn += __shfl_xor_sync(0xffffffffu, rn, 2);
                if ((lane & 3) == 0) {
                    int r = wm * 32 + mi * 16 + (lane >> 2) + h * 8;
                    atomicAdd(&s_rp[r], rp);
                    atomicAdd(&s_rn[r], rn);
                }
            }
        }
        #pragma unroll
        for (int nf = 0; nf < 8; nf++) {
            #pragma unroll
            for (int j = 0; j < 2; j++) {
                float cp = 0.f, cn = 0.f;
                #pragma unroll
                for (int mi = 0; mi < 2; mi++) {
                    float v0 = acc[mi][nf][j], v1 = acc[mi][nf][j + 2];
                    cp += fmaxf(v0, 0.f) + fmaxf(v1, 0.f);
                    cn += fmaxf(-v0, 0.f) + fmaxf(-v1, 0.f);
                }
                cp += __shfl_xor_sync(0xffffffffu, cp, 4);
                cp += __shfl_xor_sync(0xffffffffu, cp, 8);
                cp += __shfl_xor_sync(0xffffffffu, cp, 16);
                cn += __shfl_xor_sync(0xffffffffu, cn, 4);
                cn += __shfl_xor_sync(0xffffffffu, cn, 8);
                cn += __shfl_xor_sync(0xffffffffu, cn, 16);
                if (lane < 4) {
                    int c = wn * 64 + nf * 8 + lane * 2 + j;
                    atomicAdd(&s_cp[c], cp);
                    atomicAdd(&s_cn[c], cn);
                }
            }
        }
        #pragma unroll
        for (int off = 16; off; off >>= 1)
            tmax = fmaxf(tmax, __shfl_xor_sync(0xffffffffu, tmax, off));
        if (lane == 0) s_wmax[wid] = tmax;
        __syncthreads();

        if (tid < 128) {
            int gr = bm * 128 + tid;
            if (gr < MDIM) { atomicAdd(&g_rpos[gr], s_rp[tid]); atomicAdd(&g_rneg[gr], s_rn[tid]); }
            int gc = bn * 128 + tid;
            if (gc < MDIM) { atomicAdd(&g_cpos[gc], s_cp[tid]); atomicAdd(&g_cneg[gc], s_cn[tid]); }
        }
        if (tid == 0) {
            float bmax = s_wmax[0];
            #pragma unroll
            for (int w = 1; w < 8; w++) bmax = fmaxf(bmax, s_wmax[w]);
            atomicMax(&g_maxkey, fkey(bmax));
        }
        __syncthreads();   // protect s_* reuse on next tile
    }
}

// Bilinear resize (align_corners=False) with deferred 1/|M| scale + pos/neg selection.
__global__ void simcam_resize(float* __restrict__ out, int total) {
    int idx = blockIdx.x * blockDim.x + threadIdx.x;
    if (idx >= total) return;
    int p   = idx / (OUT_H * OUT_W);
    int rem = idx % (OUT_H * OUT_W);
    int oy  = rem / OUT_W;
    int ox  = rem % OUT_W;

    unsigned int key = g_maxkey;
    float Mv = (key & 0x80000000u) ? __uint_as_float(key & 0x7fffffffu)
                                   : __uint_as_float(~key);
    const float* src;
    float inv;
    if (Mv > 0.f)      { src = (p == 0) ? g_rpos : g_cpos; inv =  1.0f / Mv; }
    else if (Mv < 0.f) { src = (p == 0) ? g_rneg : g_cneg; inv = -1.0f / Mv; }
    else               { src = (p == 0) ? g_rpos : g_cpos; inv = 0.0f; }

    const float s = 72.0f / 224.0f;
    float ys = fmaxf(((float)oy + 0.5f) * s - 0.5f, 0.0f);
    float xs = fmaxf(((float)ox + 0.5f) * s - 0.5f, 0.0f);
    int y0 = (int)floorf(ys), x0 = (int)floorf(xs);
    int y1 = min(y0 + 1, 71), x1 = min(x0 + 1, 71);
    float wy = ys - (float)y0, wx = xs - (float)x0;

    float a = src[y0 * 72 + x0], b = src[y0 * 72 + x1];
    float c = src[y1 * 72 + x0], d = src[y1 * 72 + x1];
    out[idx] = (a * (1.f - wy) * (1.f - wx) + b * (1.f - wy) * wx
              + c * wy * (1.f - wx)         + d * wy * wx) * inv;
}

extern "C" void kernel_launch(void* const* d_in, const int* in_sizes, int n_in,
                              void* d_out, int out_size) {
    const float* x = (const float*)d_in[0];   // (2,72,72,256) fp32
    cudaFuncSetAttribute(simcam_gemm, cudaFuncAttributeMaxDynamicSharedMemorySize, DYN_SMEM);

    simcam_conv<<<(2 * MDIM * 128 + 255) / 256, 256>>>(x);
    simcam_gemm<<<148, 256, DYN_SMEM>>>();
    simcam_resize<<<(out_size + 255) / 256, 256>>>((float*)d_out, out_size);
}

// round 6
// speedup vs baseline: 1.4412x; 1.4412x over previous
#include <cuda_runtime.h>
#include <math_constants.h>
#include <cstdint>

// ---------------- Geometry ----------------
#define MDIM  5184          // 72*72
#define CDIM  256
#define MPAD  5248          // 41*128 = 82*64
#define NBM   41            // M tiles of 128
#define NBN   82            // N tiles of 64
#define NK    8             // K chunks of 32 bytes over 256
#define OUT_H 224
#define OUT_W 224
#define QMAX  16255.0f      // 15-bit quant range so hi limb fits s8

// smem stage: A1,A0 (128 rows x 32 B) + B1,B0 (64 rows x 32 B), row stride 48 (conflict-free ldmatrix)
#define RS      48
#define OFF_A1  0
#define OFF_A0  (128 * RS)            // 6144
#define OFF_B1  (256 * RS)            // 12288
#define OFF_B0  (256 * RS + 64 * RS)  // 15360
#define STAGE   (384 * RS)            // 18432
#define DYN_SMEM (2 * STAGE)          // 36864

// ---------------- Device scratch (allocation-free) ----------------
__device__ __align__(16) signed char g_A1[MPAD * CDIM];   // hi limbs (1.34 MB each)
__device__ __align__(16) signed char g_A0[MPAD * CDIM];
__device__ __align__(16) signed char g_B1[MPAD * CDIM];
__device__ __align__(16) signed char g_B0[MPAD * CDIM];
__device__ float        g_rpos[MDIM], g_rneg[MDIM], g_cpos[MDIM], g_cneg[MDIM];
__device__ unsigned int g_maxkey;
__device__ unsigned int g_keyA, g_keyB;     // fkey-encoded absmax (idempotent across runs)

// ---------------- PTX helpers ----------------
__device__ __forceinline__ uint32_t smem_u32(const void* p) {
    uint32_t a;
    asm("{ .reg .u64 t; cvta.to.shared.u64 t, %1; cvt.u32.u64 %0, t; }" : "=r"(a) : "l"(p));
    return a;
}
__device__ __forceinline__ unsigned int fkey(float f) {
    unsigned int u = __float_as_uint(f);
    return (u & 0x80000000u) ? ~u : (u | 0x80000000u);
}
__device__ __forceinline__ float unfkey(unsigned int k) {
    return (k & 0x80000000u) ? __uint_as_float(k & 0x7fffffffu) : __uint_as_float(~k);
}

#define CP16(dst, src) \
    asm volatile("cp.async.cg.shared.global [%0], [%1], 16;" :: "r"(dst), "l"(src))
#define CP_COMMIT()  asm volatile("cp.async.commit_group;")
#define CP_WAIT1()   asm volatile("cp.async.wait_group 1;")
#define CP_WAIT0()   asm volatile("cp.async.wait_group 0;")

#define LDSM4(r0, r1, r2, r3, a) \
    asm volatile("ldmatrix.sync.aligned.m8n8.x4.shared.b16 {%0,%1,%2,%3}, [%4];" \
                 : "=r"(r0), "=r"(r1), "=r"(r2), "=r"(r3) : "r"(a))

#define IMMA(d, a, b) \
    asm volatile("mma.sync.aligned.m16n8k32.row.col.s32.s8.s8.s32 " \
                 "{%0,%1,%2,%3}, {%4,%5,%6,%7}, {%8,%9}, {%0,%1,%2,%3};" \
                 : "+r"((d)[0]), "+r"((d)[1]), "+r"((d)[2]), "+r"((d)[3]) \
                 : "r"((a)[0]), "r"((a)[1]), "r"((a)[2]), "r"((a)[3]), \
                   "r"((b)[0]), "r"((b)[1]))

// ---------------- Kernels ----------------

// Per-tensor absmax (fkey atomicMax; idempotent across graph replays) + zero reductions + zero pads.
__global__ void simcam_absmax(const float* __restrict__ x) {
    int id = blockIdx.x * blockDim.x + threadIdx.x;     // 331776 threads
    if (id < MDIM) { g_rpos[id] = 0.f; g_rneg[id] = 0.f; g_cpos[id] = 0.f; g_cneg[id] = 0.f; }
    if (id == 0) g_maxkey = 0u;
    if (id < 4096) {   // pad rows [5184,5248) x 256 B x 4 planes = 4096 uint4
        const uint4 z = make_uint4(0u, 0u, 0u, 0u);
        int plane = id >> 10, u = id & 1023;
        signed char* p = (plane == 0) ? g_A1 : (plane == 1) ? g_A0 : (plane == 2) ? g_B1 : g_B0;
        ((uint4*)(p + (size_t)MDIM * CDIM))[u] = z;
    }
    float4 va = ((const float4*)x)[id];
    float4 vb = ((const float4*)(x + (size_t)MDIM * CDIM))[id];
    float ma = fmaxf(fmaxf(fabsf(va.x), fabsf(va.y)), fmaxf(fabsf(va.z), fabsf(va.w)));
    float mb = fmaxf(fmaxf(fabsf(vb.x), fabsf(vb.y)), fmaxf(fabsf(vb.z), fabsf(vb.w)));
    #pragma unroll
    for (int off = 16; off; off >>= 1) {
        ma = fmaxf(ma, __shfl_xor_sync(0xffffffffu, ma, off));
        mb = fmaxf(mb, __shfl_xor_sync(0xffffffffu, mb, off));
    }
    if ((threadIdx.x & 31) == 0) {
        atomicMax(&g_keyA, fkey(ma));
        atomicMax(&g_keyB, fkey(mb));
    }
}

// Quantize: V = round(x * 16255/absmax), split V = 128*A1 + A0 (both s8), planar stores.
__global__ void simcam_quant(const float* __restrict__ x) {
    int id = blockIdx.x * blockDim.x + threadIdx.x;     // 2*5184*64
    if (id >= 2 * MDIM * 64) return;
    int op  = id >= MDIM * 64;
    int rid = op ? id - MDIM * 64 : id;
    float amax = unfkey(op ? g_keyB : g_keyA);
    float inv  = (amax > 0.f) ? (QMAX / amax) : 0.f;
    float4 v = ((const float4*)(x + (size_t)op * MDIM * CDIM))[rid];
    int V[4] = { (int)rintf(v.x * inv), (int)rintf(v.y * inv),
                 (int)rintf(v.z * inv), (int)rintf(v.w * inv) };
    unsigned int p1 = 0, p0 = 0;
    #pragma unroll
    for (int j = 0; j < 4; j++) {
        int hi = (V[j] + 64) >> 7;          // [-127,127]
        int lo = V[j] - (hi << 7);          // [-64,63]
        p1 |= ((unsigned)(hi & 0xFF)) << (8 * j);
        p0 |= ((unsigned)(lo & 0xFF)) << (8 * j);
    }
    signed char* b1 = op ? g_B1 : g_A1;
    signed char* b0 = op ? g_B0 : g_A0;
    ((unsigned int*)b1)[rid] = p1;
    ((unsigned int*)b0)[rid] = p0;
}

__device__ __forceinline__ void load_stage(uint32_t sb, const signed char* A1s, const signed char* A0s,
                                           const signed char* B1s, const signed char* B0s,
                                           int kc, int tid) {
    #pragma unroll
    for (int i = 0; i < 3; i++) {
        int idx = tid + i * 256;                 // 0..767
        if (idx < 512) {                         // A1 (0..255), A0 (256..511): 128 rows x 2 halves
            int a0sel = idx >> 8;
            int r = (idx & 255) >> 1, half = idx & 1;
            const signed char* src = a0sel ? A0s : A1s;
            uint32_t dst = sb + (a0sel ? OFF_A0 : OFF_A1) + r * RS + half * 16;
            CP16(dst, src + (size_t)r * CDIM + kc * 32 + half * 16);
        } else {                                 // B1 (512..639), B0 (640..767): 64 rows x 2 halves
            int b0sel = (idx >= 640);
            int rr = (idx - (b0sel ? 640 : 512));
            int r = rr >> 1, half = rr & 1;
            const signed char* src = b0sel ? B0s : B1s;
            uint32_t dst = sb + (b0sel ? OFF_B0 : OFF_B1) + r * RS + half * 16;
            CP16(dst, src + (size_t)r * CDIM + kc * 32 + half * 16);
        }
    }
}

// Fused int8 GEMM: d ~ 16384*(A1 B1) + 128*(A1 B0 + A0 B1) per 128x64 tile,
// + relu row/col sums + global max (scale cancels in final ratio).
__global__ __launch_bounds__(256, 2) void simcam_gemm() {
    extern __shared__ unsigned char dsm[];
    __shared__ float s_rp[128], s_rn[128], s_cp[64], s_cn[64], s_wmax[8];

    const int tid  = threadIdx.x;
    const int wid  = tid >> 5, lane = tid & 31;
    const int wm   = wid & 3, wn = wid >> 2;     // 4x2 warp grid; warp tile 32(M) x 32(N)
    const int bm   = blockIdx.y, bn = blockIdx.x;

    if (tid < 128) { s_rp[tid] = 0.f; s_rn[tid] = 0.f; }
    if (tid < 64)  { s_cp[tid] = 0.f; s_cn[tid] = 0.f; }

    const signed char* A1s = g_A1 + (size_t)bm * 128 * CDIM;
    const signed char* A0s = g_A0 + (size_t)bm * 128 * CDIM;
    const signed char* B1s = g_B1 + (size_t)bn * 64 * CDIM;
    const signed char* B0s = g_B0 + (size_t)bn * 64 * CDIM;
    const uint32_t dyn = smem_u32(dsm);

    // ldmatrix lane addressing: 16 rows (lane&15) x two 16B halves (lane>>4)
    const uint32_t a_off = (uint32_t)((wm * 32 + (lane & 15)) * RS + (lane >> 4) * 16);
    const uint32_t b_off = (uint32_t)((wn * 32 + (lane & 15)) * RS + (lane >> 4) * 16);

    int acc11[2][4][4], accX[2][4][4];
    #pragma unroll
    for (int mi = 0; mi < 2; mi++)
        #pragma unroll
        for (int nf = 0; nf < 4; nf++)
            #pragma unroll
            for (int r = 0; r < 4; r++) { acc11[mi][nf][r] = 0; accX[mi][nf][r] = 0; }

    load_stage(dyn, A1s, A0s, B1s, B0s, 0, tid);
    CP_COMMIT();

    #pragma unroll 1
    for (int kc = 0; kc < NK; kc++) {
        if (kc + 1 < NK) {
            load_stage(dyn + ((kc + 1) & 1) * STAGE, A1s, A0s, B1s, B0s, kc + 1, tid);
            CP_COMMIT();
            CP_WAIT1();
        } else {
            CP_WAIT0();
        }
        __syncthreads();

        const uint32_t base = dyn + (kc & 1) * STAGE;
        uint32_t a1[2][4], a0[2][4], b1[4][2], b0[4][2];
        #pragma unroll
        for (int mi = 0; mi < 2; mi++) {
            LDSM4(a1[mi][0], a1[mi][1], a1[mi][2], a1[mi][3],
                  base + OFF_A1 + a_off + mi * (16 * RS));
            LDSM4(a0[mi][0], a0[mi][1], a0[mi][2], a0[mi][3],
                  base + OFF_A0 + a_off + mi * (16 * RS));
        }
        #pragma unroll
        for (int g = 0; g < 2; g++) {
            uint32_t r0, r1, r2, r3;
            LDSM4(r0, r1, r2, r3, base + OFF_B1 + b_off + g * (16 * RS));
            b1[2 * g][0] = r0; b1[2 * g][1] = r2;
            b1[2 * g + 1][0] = r1; b1[2 * g + 1][1] = r3;
            LDSM4(r0, r1, r2, r3, base + OFF_B0 + b_off + g * (16 * RS));
            b0[2 * g][0] = r0; b0[2 * g][1] = r2;
            b0[2 * g + 1][0] = r1; b0[2 * g + 1][1] = r3;
        }
        #pragma unroll
        for (int mi = 0; mi < 2; mi++)
            #pragma unroll
            for (int nf = 0; nf < 4; nf++) IMMA(acc11[mi][nf], a1[mi], b1[nf]);
        #pragma unroll
        for (int mi = 0; mi < 2; mi++)
            #pragma unroll
            for (int nf = 0; nf < 4; nf++) IMMA(accX[mi][nf], a1[mi], b0[nf]);
        #pragma unroll
        for (int mi = 0; mi < 2; mi++)
            #pragma unroll
            for (int nf = 0; nf < 4; nf++) IMMA(accX[mi][nf], a0[mi], b1[nf]);
        __syncthreads();
    }

    // ---- Fused epilogue (relative scale only; global quant scale cancels in sums/max ratio) ----
    // rows = wm*32 + mi*16 + (lane>>2) + h*8 ; cols = wn*32 + nf*8 + (lane&3)*2 + j
    float tmax = -CUDART_INF_F;
    const int rbase = bm * 128 + wm * 32;
    const int cbase = bn * 64 + wn * 32;

    float v[2][4][4];
    #pragma unroll
    for (int mi = 0; mi < 2; mi++)
        #pragma unroll
        for (int nf = 0; nf < 4; nf++)
            #pragma unroll
            for (int r = 0; r < 4; r++)
                v[mi][nf][r] = (float)acc11[mi][nf][r] * 16384.f + (float)accX[mi][nf][r] * 128.f;

    #pragma unroll
    for (int mi = 0; mi < 2; mi++) {
        #pragma unroll
        for (int h = 0; h < 2; h++) {
            float rp = 0.f, rn = 0.f;
            #pragma unroll
            for (int nf = 0; nf < 4; nf++) {
                float v0 = v[mi][nf][2 * h], v1 = v[mi][nf][2 * h + 1];
                rp += fmaxf(v0, 0.f) + fmaxf(v1, 0.f);
                rn += fmaxf(-v0, 0.f) + fmaxf(-v1, 0.f);
                int grow = rbase + mi * 16 + (lane >> 2) + h * 8;
                int gc0  = cbase + nf * 8 + (lane & 3) * 2;
                if (grow < MDIM && gc0 < MDIM)     tmax = fmaxf(tmax, v0);
                if (grow < MDIM && gc0 + 1 < MDIM) tmax = fmaxf(tmax, v1);
            }
            rp += __shfl_xor_sync(0xffffffffu, rp, 1); rp += __shfl_xor_sync(0xffffffffu, rp, 2);
            rn += __shfl_xor_sync(0xffffffffu, rn, 1); rn += __shfl_xor_sync(0xffffffffu, rn, 2);
            if ((lane & 3) == 0) {
                int r = wm * 32 + mi * 16 + (lane >> 2) + h * 8;
                atomicAdd(&s_rp[r], rp);
                atomicAdd(&s_rn[r], rn);
            }
        }
    }
    #pragma unroll
    for (int nf = 0; nf < 4; nf++) {
        #pragma unroll
        for (int j = 0; j < 2; j++) {
            float cp = 0.f, cn = 0.f;
            #pragma unroll
            for (int mi = 0; mi < 2; mi++) {
                float v0 = v[mi][nf][j], v1 = v[mi][nf][j + 2];
                cp += fmaxf(v0, 0.f) + fmaxf(v1, 0.f);
                cn += fmaxf(-v0, 0.f) + fmaxf(-v1, 0.f);
            }
            cp += __shfl_xor_sync(0xffffffffu, cp, 4);
            cp += __shfl_xor_sync(0xffffffffu, cp, 8);
            cp += __shfl_xor_sync(0xffffffffu, cp, 16);
            cn += __shfl_xor_sync(0xffffffffu, cn, 4);
            cn += __shfl_xor_sync(0xffffffffu, cn, 8);
            cn += __shfl_xor_sync(0xffffffffu, cn, 16);
            if (lane < 4) {
                int c = wn * 32 + nf * 8 + lane * 2 + j;
                atomicAdd(&s_cp[c], cp);
                atomicAdd(&s_cn[c], cn);
            }
        }
    }
    #pragma unroll
    for (int off = 16; off; off >>= 1)
        tmax = fmaxf(tmax, __shfl_xor_sync(0xffffffffu, tmax, off));
    if (lane == 0) s_wmax[wid] = tmax;
    __syncthreads();

    if (tid < 128) {
        int gr = bm * 128 + tid;
        if (gr < MDIM) { atomicAdd(&g_rpos[gr], s_rp[tid]); atomicAdd(&g_rneg[gr], s_rn[tid]); }
    }
    if (tid < 64) {
        int gc = bn * 64 + tid;
        if (gc < MDIM) { atomicAdd(&g_cpos[gc], s_cp[tid]); atomicAdd(&g_cneg[gc], s_cn[tid]); }
    }
    if (tid == 0) {
        float bmax = s_wmax[0];
        #pragma unroll
        for (int w = 1; w < 8; w++) bmax = fmaxf(bmax, s_wmax[w]);
        atomicMax(&g_maxkey, fkey(bmax));
    }
}

// Bilinear resize (align_corners=False) with deferred 1/|M| scale + pos/neg selection.
__global__ void simcam_resize(float* __restrict__ out, int total) {
    int idx = blockIdx.x * blockDim.x + threadIdx.x;
    if (idx >= total) return;
    int p   = idx / (OUT_H * OUT_W);
    int rem = idx % (OUT_H * OUT_W);
    int oy  = rem / OUT_W;
    int ox  = rem % OUT_W;

    float Mv = unfkey(g_maxkey);
    const float* src;
    float inv;
    if (Mv > 0.f)      { src = (p == 0) ? g_rpos : g_cpos; inv =  1.0f / Mv; }
    else if (Mv < 0.f) { src = (p == 0) ? g_rneg : g_cneg; inv = -1.0f / Mv; }
    else               { src = (p == 0) ? g_rpos : g_cpos; inv = 0.0f; }

    const float s = 72.0f / 224.0f;
    float ys = fmaxf(((float)oy + 0.5f) * s - 0.5f, 0.0f);
    float xs = fmaxf(((float)ox + 0.5f) * s - 0.5f, 0.0f);
    int y0 = (int)floorf(ys), x0 = (int)floorf(xs);
    int y1 = min(y0 + 1, 71), x1 = min(x0 + 1, 71);
    float wy = ys - (float)y0, wx = xs - (float)x0;

    float a = src[y0 * 72 + x0], b = src[y0 * 72 + x1];
    float c = src[y1 * 72 + x0], d = src[y1 * 72 + x1];
    out[idx] = (a * (1.f - wy) * (1.f - wx) + b * (1.f - wy) * wx
              + c * wy * (1.f - wx)         + d * wy * wx) * inv;
}

extern "C" void kernel_launch(void* const* d_in, const int* in_sizes, int n_in,
                              void* d_out, int out_size) {
    const float* x = (const float*)d_in[0];   // (2,72,72,256) fp32
    cudaFuncSetAttribute(simcam_gemm, cudaFuncAttributeMaxDynamicSharedMemorySize, DYN_SMEM);

    simcam_absmax<<<(MDIM * CDIM / 4) / 256, 256>>>(x);          // 1296 blocks
    simcam_quant<<<(2 * MDIM * 64 + 255) / 256, 256>>>(x);
    dim3 grid(NBN, NBM);
    simcam_gemm<<<grid, 256, DYN_SMEM>>>();
    simcam_resize<<<(out_size + 255) / 256, 256>>>((float*)d_out, out_size);
}

// round 7
// speedup vs baseline: 1.7303x; 1.2006x over previous
#include <cuda_runtime.h>
#include <math_constants.h>
#include <cstdint>

// ---------------- Geometry ----------------
#define MDIM  5184          // 72*72
#define CDIM  256
#define MPAD  5248          // 41*128 = 82*64
#define NBM   41            // M tiles of 128
#define NBN   82            // N tiles of 64
#define NK    4             // K chunks of 64 bytes over 256
#define OUT_H 224
#define OUT_W 224
#define QMAX  16255.0f      // 15-bit quant range so hi limb fits s8

// smem stage: A1,A0 (128 rows x 64 B) + B1,B0 (64 rows x 64 B), row stride 80 (conflict-free ldmatrix)
#define RS      80
#define OFF_A1  0
#define OFF_A0  (128 * RS)            // 10240
#define OFF_B1  (256 * RS)            // 20480
#define OFF_B0  (256 * RS + 64 * RS)  // 25600
#define STAGE   (384 * RS)            // 30720
#define NSTAGE  3
#define DYN_SMEM (NSTAGE * STAGE)     // 92160

// ---------------- Device scratch (allocation-free) ----------------
__device__ __align__(16) signed char g_A1[MPAD * CDIM];   // hi limbs (1.34 MB each)
__device__ __align__(16) signed char g_A0[MPAD * CDIM];
__device__ __align__(16) signed char g_B1[MPAD * CDIM];
__device__ __align__(16) signed char g_B0[MPAD * CDIM];
__device__ float        g_rpos[MDIM], g_rneg[MDIM], g_cpos[MDIM], g_cneg[MDIM];
__device__ unsigned int g_maxkey;
__device__ unsigned int g_keyA, g_keyB;     // fkey-encoded absmax (idempotent across runs)

// ---------------- PTX helpers ----------------
__device__ __forceinline__ uint32_t smem_u32(const void* p) {
    uint32_t a;
    asm("{ .reg .u64 t; cvta.to.shared.u64 t, %1; cvt.u32.u64 %0, t; }" : "=r"(a) : "l"(p));
    return a;
}
__device__ __forceinline__ unsigned int fkey(float f) {
    unsigned int u = __float_as_uint(f);
    return (u & 0x80000000u) ? ~u : (u | 0x80000000u);
}
__device__ __forceinline__ float unfkey(unsigned int k) {
    return (k & 0x80000000u) ? __uint_as_float(k & 0x7fffffffu) : __uint_as_float(~k);
}

#define CP16(dst, src) \
    asm volatile("cp.async.cg.shared.global [%0], [%1], 16;" :: "r"(dst), "l"(src))
#define CP_COMMIT()  asm volatile("cp.async.commit_group;")
#define CP_WAIT1()   asm volatile("cp.async.wait_group 1;")
#define CP_WAIT0()   asm volatile("cp.async.wait_group 0;")

#define LDSM4(r0, r1, r2, r3, a) \
    asm volatile("ldmatrix.sync.aligned.m8n8.x4.shared.b16 {%0,%1,%2,%3}, [%4];" \
                 : "=r"(r0), "=r"(r1), "=r"(r2), "=r"(r3) : "r"(a))

#define IMMA(d, a, b) \
    asm volatile("mma.sync.aligned.m16n8k32.row.col.s32.s8.s8.s32 " \
                 "{%0,%1,%2,%3}, {%4,%5,%6,%7}, {%8,%9}, {%0,%1,%2,%3};" \
                 : "+r"((d)[0]), "+r"((d)[1]), "+r"((d)[2]), "+r"((d)[3]) \
                 : "r"((a)[0]), "r"((a)[1]), "r"((a)[2]), "r"((a)[3]), \
                   "r"((b)[0]), "r"((b)[1]))

// ---------------- Kernels ----------------

// Per-tensor absmax (fkey atomicMax; idempotent across graph replays) + zero reductions + zero pads.
__global__ void simcam_absmax(const float* __restrict__ x) {
    int id = blockIdx.x * blockDim.x + threadIdx.x;     // 331776 threads
    if (id < MDIM) { g_rpos[id] = 0.f; g_rneg[id] = 0.f; g_cpos[id] = 0.f; g_cneg[id] = 0.f; }
    if (id == 0) g_maxkey = 0u;
    if (id < 4096) {   // pad rows [5184,5248) x 256 B x 4 planes = 4096 uint4
        const uint4 z = make_uint4(0u, 0u, 0u, 0u);
        int plane = id >> 10, u = id & 1023;
        signed char* p = (plane == 0) ? g_A1 : (plane == 1) ? g_A0 : (plane == 2) ? g_B1 : g_B0;
        ((uint4*)(p + (size_t)MDIM * CDIM))[u] = z;
    }
    float4 va = ((const float4*)x)[id];
    float4 vb = ((const float4*)(x + (size_t)MDIM * CDIM))[id];
    float ma = fmaxf(fmaxf(fabsf(va.x), fabsf(va.y)), fmaxf(fabsf(va.z), fabsf(va.w)));
    float mb = fmaxf(fmaxf(fabsf(vb.x), fabsf(vb.y)), fmaxf(fabsf(vb.z), fabsf(vb.w)));
    #pragma unroll
    for (int off = 16; off; off >>= 1) {
        ma = fmaxf(ma, __shfl_xor_sync(0xffffffffu, ma, off));
        mb = fmaxf(mb, __shfl_xor_sync(0xffffffffu, mb, off));
    }
    if ((threadIdx.x & 31) == 0) {
        atomicMax(&g_keyA, fkey(ma));
        atomicMax(&g_keyB, fkey(mb));
    }
}

// Quantize: V = round(x * 16255/absmax), split V = 128*A1 + A0 (both s8), planar stores.
__global__ void simcam_quant(const float* __restrict__ x) {
    int id = blockIdx.x * blockDim.x + threadIdx.x;     // 2*5184*64
    if (id >= 2 * MDIM * 64) return;
    int op  = id >= MDIM * 64;
    int rid = op ? id - MDIM * 64 : id;
    float amax = unfkey(op ? g_keyB : g_keyA);
    float inv  = (amax > 0.f) ? (QMAX / amax) : 0.f;
    float4 v = ((const float4*)(x + (size_t)op * MDIM * CDIM))[rid];
    int V[4] = { (int)rintf(v.x * inv), (int)rintf(v.y * inv),
                 (int)rintf(v.z * inv), (int)rintf(v.w * inv) };
    unsigned int p1 = 0, p0 = 0;
    #pragma unroll
    for (int j = 0; j < 4; j++) {
        int hi = (V[j] + 64) >> 7;          // [-127,127]
        int lo = V[j] - (hi << 7);          // [-64,63]
        p1 |= ((unsigned)(hi & 0xFF)) << (8 * j);
        p0 |= ((unsigned)(lo & 0xFF)) << (8 * j);
    }
    signed char* b1 = op ? g_B1 : g_A1;
    signed char* b0 = op ? g_B0 : g_A0;
    ((unsigned int*)b1)[rid] = p1;
    ((unsigned int*)b0)[rid] = p0;
}

// Stage load: 1536 CP16 total = 6 per thread. A planes 128 rows x 64 B, B planes 64 rows x 64 B.
__device__ __forceinline__ void load_stage(uint32_t sb, const signed char* A1s, const signed char* A0s,
                                           const signed char* B1s, const signed char* B0s,
                                           int kc, int tid) {
    #pragma unroll
    for (int i = 0; i < 6; i++) {
        int idx = tid + i * 256;                 // 0..1535
        if (idx < 1024) {                        // A1 (0..511), A0 (512..1023): 128 rows x 4 chunks
            int a0sel = idx >> 9;
            int r = (idx & 511) >> 2, q = idx & 3;
            const signed char* src = a0sel ? A0s : A1s;
            uint32_t dst = sb + (a0sel ? OFF_A0 : OFF_A1) + r * RS + q * 16;
            CP16(dst, src + (size_t)r * CDIM + kc * 64 + q * 16);
        } else {                                 // B1 (1024..1279), B0 (1280..1535): 64 rows x 4 chunks
            int b0sel = (idx >= 1280);
            int rr = idx - (b0sel ? 1280 : 1024);
            int r = rr >> 2, q = rr & 3;
            const signed char* src = b0sel ? B0s : B1s;
            uint32_t dst = sb + (b0sel ? OFF_B0 : OFF_B1) + r * RS + q * 16;
            CP16(dst, src + (size_t)r * CDIM + kc * 64 + q * 16);
        }
    }
}

// Fused int8 GEMM: d ~ 16384*(A1 B1) + 128*(A1 B0 + A0 B1) per 128x64 tile,
// + relu row/col sums + global max (scale cancels in final ratio).
__global__ __launch_bounds__(256, 2) void simcam_gemm() {
    extern __shared__ unsigned char dsm[];
    __shared__ float s_rp[128], s_rn[128], s_cp[64], s_cn[64], s_wmax[8];

    const int tid  = threadIdx.x;
    const int wid  = tid >> 5, lane = tid & 31;
    const int wm   = wid & 3, wn = wid >> 2;     // 4x2 warp grid; warp tile 32(M) x 32(N)
    const int bm   = blockIdx.y, bn = blockIdx.x;

    if (tid < 128) { s_rp[tid] = 0.f; s_rn[tid] = 0.f; }
    if (tid < 64)  { s_cp[tid] = 0.f; s_cn[tid] = 0.f; }

    const signed char* A1s = g_A1 + (size_t)bm * 128 * CDIM;
    const signed char* A0s = g_A0 + (size_t)bm * 128 * CDIM;
    const signed char* B1s = g_B1 + (size_t)bn * 64 * CDIM;
    const signed char* B0s = g_B0 + (size_t)bn * 64 * CDIM;
    const uint32_t dyn = smem_u32(dsm);

    // ldmatrix lane addressing: 16 rows (lane&15) x two 16B halves (lane>>4)
    const uint32_t a_off = (uint32_t)((wm * 32 + (lane & 15)) * RS + (lane >> 4) * 16);
    const uint32_t b_off = (uint32_t)((wn * 32 + (lane & 15)) * RS + (lane >> 4) * 16);

    int acc11[2][4][4], accX[2][4][4];
    #pragma unroll
    for (int mi = 0; mi < 2; mi++)
        #pragma unroll
        for (int nf = 0; nf < 4; nf++)
            #pragma unroll
            for (int r = 0; r < 4; r++) { acc11[mi][nf][r] = 0; accX[mi][nf][r] = 0; }

    // Prologue: stages 0 and 1 in flight.
    load_stage(dyn + 0 * STAGE, A1s, A0s, B1s, B0s, 0, tid);
    CP_COMMIT();
    load_stage(dyn + 1 * STAGE, A1s, A0s, B1s, B0s, 1, tid);
    CP_COMMIT();

    #pragma unroll
    for (int kc = 0; kc < NK; kc++) {
        // Stage kc ready (own groups), then barrier: doubles as read-protection for the
        // buffer (kc+2)%3 we are about to overwrite (its old contents were consumed at kc-1).
        if (kc < NK - 1) CP_WAIT1(); else CP_WAIT0();
        __syncthreads();
        if (kc + 2 < NK) {
            load_stage(dyn + ((kc + 2) % NSTAGE) * STAGE, A1s, A0s, B1s, B0s, kc + 2, tid);
            CP_COMMIT();
        }

        const uint32_t base = dyn + (kc % NSTAGE) * STAGE;
        #pragma unroll
        for (int s = 0; s < 2; s++) {        // two k32 sub-chunks of the 64-byte chunk
            uint32_t a1[2][4], a0[2][4], b1[4][2], b0[4][2];
            #pragma unroll
            for (int mi = 0; mi < 2; mi++) {
                LDSM4(a1[mi][0], a1[mi][1], a1[mi][2], a1[mi][3],
                      base + OFF_A1 + a_off + mi * (16 * RS) + s * 32);
                LDSM4(a0[mi][0], a0[mi][1], a0[mi][2], a0[mi][3],
                      base + OFF_A0 + a_off + mi * (16 * RS) + s * 32);
            }
            #pragma unroll
            for (int g = 0; g < 2; g++) {
                uint32_t r0, r1, r2, r3;
                LDSM4(r0, r1, r2, r3, base + OFF_B1 + b_off + g * (16 * RS) + s * 32);
                b1[2 * g][0] = r0; b1[2 * g][1] = r2;
                b1[2 * g + 1][0] = r1; b1[2 * g + 1][1] = r3;
                LDSM4(r0, r1, r2, r3, base + OFF_B0 + b_off + g * (16 * RS) + s * 32);
                b0[2 * g][0] = r0; b0[2 * g][1] = r2;
                b0[2 * g + 1][0] = r1; b0[2 * g + 1][1] = r3;
            }
            #pragma unroll
            for (int mi = 0; mi < 2; mi++)
                #pragma unroll
                for (int nf = 0; nf < 4; nf++) IMMA(acc11[mi][nf], a1[mi], b1[nf]);
            #pragma unroll
            for (int mi = 0; mi < 2; mi++)
                #pragma unroll
                for (int nf = 0; nf < 4; nf++) IMMA(accX[mi][nf], a1[mi], b0[nf]);
            #pragma unroll
            for (int mi = 0; mi < 2; mi++)
                #pragma unroll
                for (int nf = 0; nf < 4; nf++) IMMA(accX[mi][nf], a0[mi], b1[nf]);
        }
    }

    // ---- Fused epilogue (relative scale only; global quant scale cancels in sums/max ratio) ----
    // rows = wm*32 + mi*16 + (lane>>2) + h*8 ; cols = wn*32 + nf*8 + (lane&3)*2 + j
    float tmax = -CUDART_INF_F;
    const int rbase = bm * 128 + wm * 32;
    const int cbase = bn * 64 + wn * 32;

    float v[2][4][4];
    #pragma unroll
    for (int mi = 0; mi < 2; mi++)
        #pragma unroll
        for (int nf = 0; nf < 4; nf++)
            #pragma unroll
            for (int r = 0; r < 4; r++)
                v[mi][nf][r] = (float)acc11[mi][nf][r] * 16384.f + (float)accX[mi][nf][r] * 128.f;

    #pragma unroll
    for (int mi = 0; mi < 2; mi++) {
        #pragma unroll
        for (int h = 0; h < 2; h++) {
            float rp = 0.f, rn = 0.f;
            #pragma unroll
            for (int nf = 0; nf < 4; nf++) {
                float v0 = v[mi][nf][2 * h], v1 = v[mi][nf][2 * h + 1];
                rp += fmaxf(v0, 0.f) + fmaxf(v1, 0.f);
                rn += fmaxf(-v0, 0.f) + fmaxf(-v1, 0.f);
                int grow = rbase + mi * 16 + (lane >> 2) + h * 8;
                int gc0  = cbase + nf * 8 + (lane & 3) * 2;
                if (grow < MDIM && gc0 < MDIM)     tmax = fmaxf(tmax, v0);
                if (grow < MDIM && gc0 + 1 < MDIM) tmax = fmaxf(tmax, v1);
            }
            rp += __shfl_xor_sync(0xffffffffu, rp, 1); rp += __shfl_xor_sync(0xffffffffu, rp, 2);
            rn += __shfl_xor_sync(0xffffffffu, rn, 1); rn += __shfl_xor_sync(0xffffffffu, rn, 2);
            if ((lane & 3) == 0) {
                int r = wm * 32 + mi * 16 + (lane >> 2) + h * 8;
                atomicAdd(&s_rp[r], rp);
                atomicAdd(&s_rn[r], rn);
            }
        }
    }
    #pragma unroll
    for (int nf = 0; nf < 4; nf++) {
        #pragma unroll
        for (int j = 0; j < 2; j++) {
            float cp = 0.f, cn = 0.f;
            #pragma unroll
            for (int mi = 0; mi < 2; mi++) {
                float v0 = v[mi][nf][j], v1 = v[mi][nf][j + 2];
                cp += fmaxf(v0, 0.f) + fmaxf(v1, 0.f);
                cn += fmaxf(-v0, 0.f) + fmaxf(-v1, 0.f);
            }
            cp += __shfl_xor_sync(0xffffffffu, cp, 4);
            cp += __shfl_xor_sync(0xffffffffu, cp, 8);
            cp += __shfl_xor_sync(0xffffffffu, cp, 16);
            cn += __shfl_xor_sync(0xffffffffu, cn, 4);
            cn += __shfl_xor_sync(0xffffffffu, cn, 8);
            cn += __shfl_xor_sync(0xffffffffu, cn, 16);
            if (lane < 4) {
                int c = wn * 32 + nf * 8 + lane * 2 + j;
                atomicAdd(&s_cp[c], cp);
                atomicAdd(&s_cn[c], cn);
            }
        }
    }
    #pragma unroll
    for (int off = 16; off; off >>= 1)
        tmax = fmaxf(tmax, __shfl_xor_sync(0xffffffffu, tmax, off));
    if (lane == 0) s_wmax[wid] = tmax;
    __syncthreads();

    if (tid < 128) {
        int gr = bm * 128 + tid;
        if (gr < MDIM) { atomicAdd(&g_rpos[gr], s_rp[tid]); atomicAdd(&g_rneg[gr], s_rn[tid]); }
    }
    if (tid < 64) {
        int gc = bn * 64 + tid;
        if (gc < MDIM) { atomicAdd(&g_cpos[gc], s_cp[tid]); atomicAdd(&g_cneg[gc], s_cn[tid]); }
    }
    if (tid == 0) {
        float bmax = s_wmax[0];
        #pragma unroll
        for (int w = 1; w < 8; w++) bmax = fmaxf(bmax, s_wmax[w]);
        atomicMax(&g_maxkey, fkey(bmax));
    }
}

// Bilinear resize (align_corners=False) with deferred 1/|M| scale + pos/neg selection.
__global__ void simcam_resize(float* __restrict__ out, int total) {
    int idx = blockIdx.x * blockDim.x + threadIdx.x;
    if (idx >= total) return;
    int p   = idx / (OUT_H * OUT_W);
    int rem = idx % (OUT_H * OUT_W);
    int oy  = rem / OUT_W;
    int ox  = rem % OUT_W;

    float Mv = unfkey(g_maxkey);
    const float* src;
    float inv;
    if (Mv > 0.f)      { src = (p == 0) ? g_rpos : g_cpos; inv =  1.0f / Mv; }
    else if (Mv < 0.f) { src = (p == 0) ? g_rneg : g_cneg; inv = -1.0f / Mv; }
    else               { src = (p == 0) ? g_rpos : g_cpos; inv = 0.0f; }

    const float s = 72.0f / 224.0f;
    float ys = fmaxf(((float)oy + 0.5f) * s - 0.5f, 0.0f);
    float xs = fmaxf(((float)ox + 0.5f) * s - 0.5f, 0.0f);
    int y0 = (int)floorf(ys), x0 = (int)floorf(xs);
    int y1 = min(y0 + 1, 71), x1 = min(x0 + 1, 71);
    float wy = ys - (float)y0, wx = xs - (float)x0;

    float a = src[y0 * 72 + x0], b = src[y0 * 72 + x1];
    float c = src[y1 * 72 + x0], d = src[y1 * 72 + x1];
    out[idx] = (a * (1.f - wy) * (1.f - wx) + b * (1.f - wy) * wx
              + c * wy * (1.f - wx)         + d * wy * wx) * inv;
}

extern "C" void kernel_launch(void* const* d_in, const int* in_sizes, int n_in,
                              void* d_out, int out_size) {
    const float* x = (const float*)d_in[0];   // (2,72,72,256) fp32
    cudaFuncSetAttribute(simcam_gemm, cudaFuncAttributeMaxDynamicSharedMemorySize, DYN_SMEM);

    simcam_absmax<<<(MDIM * CDIM / 4) / 256, 256>>>(x);          // 1296 blocks
    simcam_quant<<<(2 * MDIM * 64 + 255) / 256, 256>>>(x);
    dim3 grid(NBN, NBM);
    simcam_gemm<<<grid, 256, DYN_SMEM>>>();
    simcam_resize<<<(out_size + 255) / 256, 256>>>((float*)d_out, out_size);
}

// round 8
// speedup vs baseline: 1.9379x; 1.1200x over previous
#include <cuda_runtime.h>
#include <math_constants.h>
#include <cstdint>

// ---------------- Geometry ----------------
#define MDIM  5184          // 72*72
#define CDIM  256
#define MPAD  5248          // 41*128 = 82*64
#define NBM   41            // M tiles of 128
#define NBN   82            // N tiles of 64
#define OUT_H 224
#define OUT_W 224
#define QMAX  16255.0f      // 15-bit quant range so hi limb fits s8

// smem stage (BK = 128 bytes of K): A1,A0 128 rows x 128 B; B1,B0 64 rows x 128 B.
// XOR swizzle (chunk' = chunk ^ (row & 7)) -> conflict-free ldmatrix, zero padding.
#define OFF_A1  0
#define OFF_A0  16384
#define OFF_B1  32768
#define OFF_B0  40960
#define STAGE   49152
#define DYN_SMEM (2 * STAGE)          // 98304; whole K=256 in two stages

// ---------------- Device scratch (allocation-free) ----------------
__device__ __align__(16) signed char g_A1[MPAD * CDIM];   // hi limbs (1.34 MB each)
__device__ __align__(16) signed char g_A0[MPAD * CDIM];
__device__ __align__(16) signed char g_B1[MPAD * CDIM];
__device__ __align__(16) signed char g_B0[MPAD * CDIM];
__device__ float        g_rpos[MDIM], g_rneg[MDIM], g_cpos[MDIM], g_cneg[MDIM];
__device__ unsigned int g_maxkey;
__device__ unsigned int g_keyA, g_keyB;     // fkey-encoded absmax (idempotent across runs)

// ---------------- PTX helpers ----------------
__device__ __forceinline__ uint32_t smem_u32(const void* p) {
    uint32_t a;
    asm("{ .reg .u64 t; cvta.to.shared.u64 t, %1; cvt.u32.u64 %0, t; }" : "=r"(a) : "l"(p));
    return a;
}
__device__ __forceinline__ unsigned int fkey(float f) {
    unsigned int u = __float_as_uint(f);
    return (u & 0x80000000u) ? ~u : (u | 0x80000000u);
}
__device__ __forceinline__ float unfkey(unsigned int k) {
    return (k & 0x80000000u) ? __uint_as_float(k & 0x7fffffffu) : __uint_as_float(~k);
}

#define CP16(dst, src) \
    asm volatile("cp.async.cg.shared.global [%0], [%1], 16;" :: "r"(dst), "l"(src))
#define CP_COMMIT()  asm volatile("cp.async.commit_group;")
#define CP_WAIT1()   asm volatile("cp.async.wait_group 1;")
#define CP_WAIT0()   asm volatile("cp.async.wait_group 0;")

#define LDSM4(r0, r1, r2, r3, a) \
    asm volatile("ldmatrix.sync.aligned.m8n8.x4.shared.b16 {%0,%1,%2,%3}, [%4];" \
                 : "=r"(r0), "=r"(r1), "=r"(r2), "=r"(r3) : "r"(a))

#define IMMA(d, a, b) \
    asm volatile("mma.sync.aligned.m16n8k32.row.col.s32.s8.s8.s32 " \
                 "{%0,%1,%2,%3}, {%4,%5,%6,%7}, {%8,%9}, {%0,%1,%2,%3};" \
                 : "+r"((d)[0]), "+r"((d)[1]), "+r"((d)[2]), "+r"((d)[3]) \
                 : "r"((a)[0]), "r"((a)[1]), "r"((a)[2]), "r"((a)[3]), \
                   "r"((b)[0]), "r"((b)[1]))

// ---------------- Kernels ----------------

// Per-tensor absmax (fkey atomicMax; idempotent across graph replays) + zero reductions + zero pads.
__global__ void simcam_absmax(const float* __restrict__ x) {
    int id = blockIdx.x * blockDim.x + threadIdx.x;     // 331776 threads
    if (id < MDIM) { g_rpos[id] = 0.f; g_rneg[id] = 0.f; g_cpos[id] = 0.f; g_cneg[id] = 0.f; }
    if (id == 0) g_maxkey = 0u;
    if (id < 4096) {   // pad rows [5184,5248) x 256 B x 4 planes = 4096 uint4
        const uint4 z = make_uint4(0u, 0u, 0u, 0u);
        int plane = id >> 10, u = id & 1023;
        signed char* p = (plane == 0) ? g_A1 : (plane == 1) ? g_A0 : (plane == 2) ? g_B1 : g_B0;
        ((uint4*)(p + (size_t)MDIM * CDIM))[u] = z;
    }
    float4 va = ((const float4*)x)[id];
    float4 vb = ((const float4*)(x + (size_t)MDIM * CDIM))[id];
    float ma = fmaxf(fmaxf(fabsf(va.x), fabsf(va.y)), fmaxf(fabsf(va.z), fabsf(va.w)));
    float mb = fmaxf(fmaxf(fabsf(vb.x), fabsf(vb.y)), fmaxf(fabsf(vb.z), fabsf(vb.w)));
    #pragma unroll
    for (int off = 16; off; off >>= 1) {
        ma = fmaxf(ma, __shfl_xor_sync(0xffffffffu, ma, off));
        mb = fmaxf(mb, __shfl_xor_sync(0xffffffffu, mb, off));
    }
    if ((threadIdx.x & 31) == 0) {
        atomicMax(&g_keyA, fkey(ma));
        atomicMax(&g_keyB, fkey(mb));
    }
}

// Quantize: V = round(x * 16255/absmax), split V = 128*A1 + A0 (both s8), planar stores.
__global__ void simcam_quant(const float* __restrict__ x) {
    int id = blockIdx.x * blockDim.x + threadIdx.x;     // 2*5184*64
    if (id >= 2 * MDIM * 64) return;
    int op  = id >= MDIM * 64;
    int rid = op ? id - MDIM * 64 : id;
    float amax = unfkey(op ? g_keyB : g_keyA);
    float inv  = (amax > 0.f) ? (QMAX / amax) : 0.f;
    float4 v = ((const float4*)(x + (size_t)op * MDIM * CDIM))[rid];
    int V[4] = { (int)rintf(v.x * inv), (int)rintf(v.y * inv),
                 (int)rintf(v.z * inv), (int)rintf(v.w * inv) };
    unsigned int p1 = 0, p0 = 0;
    #pragma unroll
    for (int j = 0; j < 4; j++) {
        int hi = (V[j] + 64) >> 7;          // [-127,127]
        int lo = V[j] - (hi << 7);          // [-64,63]
        p1 |= ((unsigned)(hi & 0xFF)) << (8 * j);
        p0 |= ((unsigned)(lo & 0xFF)) << (8 * j);
    }
    signed char* b1 = op ? g_B1 : g_A1;
    signed char* b0 = op ? g_B0 : g_A0;
    ((unsigned int*)b1)[rid] = p1;
    ((unsigned int*)b0)[rid] = p0;
}

// Stage load: 3072 CP16 = 12 per thread. Swizzled dst: chunk' = chunk ^ (row & 7).
__device__ __forceinline__ void load_stage(uint32_t sb, const signed char* A1s, const signed char* A0s,
                                           const signed char* B1s, const signed char* B0s,
                                           int kc, int tid) {
    #pragma unroll
    for (int i = 0; i < 12; i++) {
        int idx = tid + i * 256;                 // 0..3071
        const signed char* src;
        uint32_t off;
        int r, q;
        if (idx < 2048) {                        // A1 (0..1023), A0 (1024..2047): 128 rows x 8 chunks
            int w = idx & 1023;
            r = w >> 3; q = w & 7;
            src = (idx < 1024) ? A1s : A0s;
            off = (idx < 1024) ? OFF_A1 : OFF_A0;
        } else {                                 // B1, B0: 64 rows x 8 chunks each
            int w = idx - 2048;
            int ww = w & 511;
            r = ww >> 3; q = ww & 7;
            src = (w < 512) ? B1s : B0s;
            off = (w < 512) ? OFF_B1 : OFF_B0;
        }
        uint32_t dst = sb + off + (uint32_t)(r * 128 + ((q ^ (r & 7)) * 16));
        CP16(dst, src + (size_t)r * CDIM + kc * 128 + q * 16);
    }
}

// Fused int8 GEMM: d ~ 16384*(A1 B1) + 128*(A1 B0 + A0 B1) per 128x64 tile,
// + relu row/col sums + global max (scale cancels in final ratio).
__global__ __launch_bounds__(256, 2) void simcam_gemm() {
    extern __shared__ unsigned char dsm[];
    __shared__ float s_rp[128], s_rn[128], s_cp[64], s_cn[64], s_wmax[8];

    const int tid  = threadIdx.x;
    const int wid  = tid >> 5, lane = tid & 31;
    const int wm   = wid & 3, wn = wid >> 2;     // 4x2 warp grid; warp tile 32(M) x 32(N)
    const int bm   = blockIdx.y, bn = blockIdx.x;

    if (tid < 128) { s_rp[tid] = 0.f; s_rn[tid] = 0.f; }
    if (tid < 64)  { s_cp[tid] = 0.f; s_cn[tid] = 0.f; }

    const signed char* A1s = g_A1 + (size_t)bm * 128 * CDIM;
    const signed char* A0s = g_A0 + (size_t)bm * 128 * CDIM;
    const signed char* B1s = g_B1 + (size_t)bn * 64 * CDIM;
    const signed char* B0s = g_B0 + (size_t)bn * 64 * CDIM;
    const uint32_t dyn = smem_u32(dsm);

    // ldmatrix lane addressing (16 rows x two 16B chunk-slots, swizzled per row)
    const uint32_t arow = (uint32_t)((wm * 32 + (lane & 15)) * 128);
    const uint32_t brow = (uint32_t)((wn * 32 + (lane & 15)) * 128);
    const int      cx   = lane >> 4;             // chunk slot 0/1
    const int      swz  = lane & 7;              // row-dependent XOR key

    int acc11[2][4][4], accX[2][4][4];
    #pragma unroll
    for (int mi = 0; mi < 2; mi++)
        #pragma unroll
        for (int nf = 0; nf < 4; nf++)
            #pragma unroll
            for (int r = 0; r < 4; r++) { acc11[mi][nf][r] = 0; accX[mi][nf][r] = 0; }

    // Issue BOTH stages (whole K) up front; stage1 streams in behind stage0's compute.
    load_stage(dyn + 0 * STAGE, A1s, A0s, B1s, B0s, 0, tid);
    CP_COMMIT();
    load_stage(dyn + 1 * STAGE, A1s, A0s, B1s, B0s, 1, tid);
    CP_COMMIT();

    #pragma unroll
    for (int kc = 0; kc < 2; kc++) {
        if (kc == 0) CP_WAIT1(); else CP_WAIT0();
        __syncthreads();
        const uint32_t base = dyn + kc * STAGE;
        #pragma unroll
        for (int s = 0; s < 4; s++) {            // four k32 sub-chunks of 128 bytes
            const uint32_t ca = (uint32_t)(((2 * s + cx) ^ swz) << 4);
            uint32_t a1[2][4], a0[2][4], b1[4][2], b0[4][2];
            #pragma unroll
            for (int mi = 0; mi < 2; mi++) {
                LDSM4(a1[mi][0], a1[mi][1], a1[mi][2], a1[mi][3],
                      base + OFF_A1 + arow + mi * 2048 + ca);
                LDSM4(a0[mi][0], a0[mi][1], a0[mi][2], a0[mi][3],
                      base + OFF_A0 + arow + mi * 2048 + ca);
            }
            #pragma unroll
            for (int g = 0; g < 2; g++) {
                uint32_t r0, r1, r2, r3;
                LDSM4(r0, r1, r2, r3, base + OFF_B1 + brow + g * 2048 + ca);
                b1[2 * g][0] = r0; b1[2 * g][1] = r2;
                b1[2 * g + 1][0] = r1; b1[2 * g + 1][1] = r3;
                LDSM4(r0, r1, r2, r3, base + OFF_B0 + brow + g * 2048 + ca);
                b0[2 * g][0] = r0; b0[2 * g][1] = r2;
                b0[2 * g + 1][0] = r1; b0[2 * g + 1][1] = r3;
            }
            #pragma unroll
            for (int mi = 0; mi < 2; mi++)
                #pragma unroll
                for (int nf = 0; nf < 4; nf++) IMMA(acc11[mi][nf], a1[mi], b1[nf]);
            #pragma unroll
            for (int mi = 0; mi < 2; mi++)
                #pragma unroll
                for (int nf = 0; nf < 4; nf++) IMMA(accX[mi][nf], a1[mi], b0[nf]);
            #pragma unroll
            for (int mi = 0; mi < 2; mi++)
                #pragma unroll
                for (int nf = 0; nf < 4; nf++) IMMA(accX[mi][nf], a0[mi], b1[nf]);
        }
    }

    // ---- Fused epilogue (conversion inline; global quant scale cancels in sums/max ratio) ----
    // rows = wm*32 + mi*16 + (lane>>2) + h*8 ; cols = wn*32 + nf*8 + (lane&3)*2 + j
    float tmax = -CUDART_INF_F;
    const int rbase = bm * 128 + wm * 32;
    const int cbase = bn * 64 + wn * 32;

    #pragma unroll
    for (int mi = 0; mi < 2; mi++) {
        #pragma unroll
        for (int h = 0; h < 2; h++) {
            float rp = 0.f, rn = 0.f;
            #pragma unroll
            for (int nf = 0; nf < 4; nf++) {
                float v0 = (float)acc11[mi][nf][2 * h] * 16384.f + (float)accX[mi][nf][2 * h] * 128.f;
                float v1 = (float)acc11[mi][nf][2 * h + 1] * 16384.f + (float)accX[mi][nf][2 * h + 1] * 128.f;
                rp += fmaxf(v0, 0.f) + fmaxf(v1, 0.f);
                rn += fmaxf(-v0, 0.f) + fmaxf(-v1, 0.f);
                int grow = rbase + mi * 16 + (lane >> 2) + h * 8;
                int gc0  = cbase + nf * 8 + (lane & 3) * 2;
                if (grow < MDIM && gc0 < MDIM)     tmax = fmaxf(tmax, v0);
                if (grow < MDIM && gc0 + 1 < MDIM) tmax = fmaxf(tmax, v1);
            }
            rp += __shfl_xor_sync(0xffffffffu, rp, 1); rp += __shfl_xor_sync(0xffffffffu, rp, 2);
            rn += __shfl_xor_sync(0xffffffffu, rn, 1); rn += __shfl_xor_sync(0xffffffffu, rn, 2);
            if ((lane & 3) == 0) {
                int r = wm * 32 + mi * 16 + (lane >> 2) + h * 8;
                atomicAdd(&s_rp[r], rp);
                atomicAdd(&s_rn[r], rn);
            }
        }
    }
    #pragma unroll
    for (int nf = 0; nf < 4; nf++) {
        #pragma unroll
        for (int j = 0; j < 2; j++) {
            float cp = 0.f, cn = 0.f;
            #pragma unroll
            for (int mi = 0; mi < 2; mi++) {
                float v0 = (float)acc11[mi][nf][j] * 16384.f + (float)accX[mi][nf][j] * 128.f;
                float v1 = (float)acc11[mi][nf][j + 2] * 16384.f + (float)accX[mi][nf][j + 2] * 128.f;
                cp += fmaxf(v0, 0.f) + fmaxf(v1, 0.f);
                cn += fmaxf(-v0, 0.f) + fmaxf(-v1, 0.f);
            }
            cp += __shfl_xor_sync(0xffffffffu, cp, 4);
            cp += __shfl_xor_sync(0xffffffffu, cp, 8);
            cp += __shfl_xor_sync(0xffffffffu, cp, 16);
            cn += __shfl_xor_sync(0xffffffffu, cn, 4);
            cn += __shfl_xor_sync(0xffffffffu, cn, 8);
            cn += __shfl_xor_sync(0xffffffffu, cn, 16);
            if (lane < 4) {
                int c = wn * 32 + nf * 8 + lane * 2 + j;
                atomicAdd(&s_cp[c], cp);
                atomicAdd(&s_cn[c], cn);
            }
        }
    }
    #pragma unroll
    for (int off = 16; off; off >>= 1)
        tmax = fmaxf(tmax, __shfl_xor_sync(0xffffffffu, tmax, off));
    if (lane == 0) s_wmax[wid] = tmax;
    __syncthreads();

    if (tid < 128) {
        int gr = bm * 128 + tid;
        if (gr < MDIM) { atomicAdd(&g_rpos[gr], s_rp[tid]); atomicAdd(&g_rneg[gr], s_rn[tid]); }
    }
    if (tid < 64) {
        int gc = bn * 64 + tid;
        if (gc < MDIM) { atomicAdd(&g_cpos[gc], s_cp[tid]); atomicAdd(&g_cneg[gc], s_cn[tid]); }
    }
    if (tid == 0) {
        float bmax = s_wmax[0];
        #pragma unroll
        for (int w = 1; w < 8; w++) bmax = fmaxf(bmax, s_wmax[w]);
        atomicMax(&g_maxkey, fkey(bmax));
    }
}

// Bilinear resize (align_corners=False) with deferred 1/|M| scale + pos/neg selection.
__global__ void simcam_resize(float* __restrict__ out, int total) {
    int idx = blockIdx.x * blockDim.x + threadIdx.x;
    if (idx >= total) return;
    int p   = idx / (OUT_H * OUT_W);
    int rem = idx % (OUT_H * OUT_W);
    int oy  = rem / OUT_W;
    int ox  = rem % OUT_W;

    float Mv = unfkey(g_maxkey);
    const float* src;
    float inv;
    if (Mv > 0.f)      { src = (p == 0) ? g_rpos : g_cpos; inv =  1.0f / Mv; }
    else if (Mv < 0.f) { src = (p == 0) ? g_rneg : g_cneg; inv = -1.0f / Mv; }
    else               { src = (p == 0) ? g_rpos : g_cpos; inv = 0.0f; }

    const float s = 72.0f / 224.0f;
    float ys = fmaxf(((float)oy + 0.5f) * s - 0.5f, 0.0f);
    float xs = fmaxf(((float)ox + 0.5f) * s - 0.5f, 0.0f);
    int y0 = (int)floorf(ys), x0 = (int)floorf(xs);
    int y1 = min(y0 + 1, 71), x1 = min(x0 + 1, 71);
    float wy = ys - (float)y0, wx = xs - (float)x0;

    float a = src[y0 * 72 + x0], b = src[y0 * 72 + x1];
    float c = src[y1 * 72 + x0], d = src[y1 * 72 + x1];
    out[idx] = (a * (1.f - wy) * (1.f - wx) + b * (1.f - wy) * wx
              + c * wy * (1.f - wx)         + d * wy * wx) * inv;
}

extern "C" void kernel_launch(void* const* d_in, const int* in_sizes, int n_in,
                              void* d_out, int out_size) {
    const float* x = (const float*)d_in[0];   // (2,72,72,256) fp32
    cudaFuncSetAttribute(simcam_gemm, cudaFuncAttributeMaxDynamicSharedMemorySize, DYN_SMEM);

    simcam_absmax<<<(MDIM * CDIM / 4) / 256, 256>>>(x);          // 1296 blocks
    simcam_quant<<<(2 * MDIM * 64 + 255) / 256, 256>>>(x);
    dim3 grid(NBN, NBM);
    simcam_gemm<<<grid, 256, DYN_SMEM>>>();
    simcam_resize<<<(out_size + 255) / 256, 256>>>((float*)d_out, out_size);
}

// round 9
// speedup vs baseline: 2.1029x; 1.0851x over previous
#include <cuda_runtime.h>
#include <math_constants.h>
#include <cstdint>

// ---------------- Geometry ----------------
#define MDIM  5184          // 72*72
#define CDIM  256
#define MPAD  5248          // 41*128 (M padded); N needs no pad: 5184 = 81*64
#define NBM   41            // M tiles of 128 (last tile half pad)
#define NBN   81            // N tiles of 64, exact
#define OUT_H 224
#define OUT_W 224
#define QMAX  16255.0f      // 15-bit quant range so hi limb fits s8
#define NPREP 592           // prep grid: 4 blocks/SM, guaranteed co-resident

// smem stage (BK = 128 bytes of K): A1,A0 128 rows x 128 B; B1,B0 64 rows x 128 B.
// XOR swizzle (chunk' = chunk ^ (row & 7)) -> conflict-free ldmatrix, zero padding.
#define OFF_A1  0
#define OFF_A0  16384
#define OFF_B1  32768
#define OFF_B0  40960
#define STAGE   49152
#define DYN_SMEM (2 * STAGE)          // 98304; whole K=256 in two stages

// ---------------- Device scratch (allocation-free) ----------------
__device__ __align__(16) signed char g_A1[MPAD * CDIM];   // hi limbs
__device__ __align__(16) signed char g_A0[MPAD * CDIM];
__device__ __align__(16) signed char g_B1[MPAD * CDIM];
__device__ __align__(16) signed char g_B0[MPAD * CDIM];
__device__ float        g_rpos[MDIM], g_rneg[MDIM], g_cpos[MDIM], g_cneg[MDIM];
__device__ unsigned int g_maxkey;
__device__ unsigned int g_keyA, g_keyB;     // fkey-encoded absmax (idempotent across runs)
__device__ unsigned int g_ctr;              // prep barrier counter (reset by resize each run)

// ---------------- PTX helpers ----------------
__device__ __forceinline__ uint32_t smem_u32(const void* p) {
    uint32_t a;
    asm("{ .reg .u64 t; cvta.to.shared.u64 t, %1; cvt.u32.u64 %0, t; }" : "=r"(a) : "l"(p));
    return a;
}
__device__ __forceinline__ unsigned int fkey(float f) {
    unsigned int u = __float_as_uint(f);
    return (u & 0x80000000u) ? ~u : (u | 0x80000000u);
}
__device__ __forceinline__ float unfkey(unsigned int k) {
    return (k & 0x80000000u) ? __uint_as_float(k & 0x7fffffffu) : __uint_as_float(~k);
}

#define CP16(dst, src) \
    asm volatile("cp.async.cg.shared.global [%0], [%1], 16;" :: "r"(dst), "l"(src))
#define CP_COMMIT()  asm volatile("cp.async.commit_group;")
#define CP_WAIT1()   asm volatile("cp.async.wait_group 1;")
#define CP_WAIT0()   asm volatile("cp.async.wait_group 0;")

#define LDSM4(r0, r1, r2, r3, a) \
    asm volatile("ldmatrix.sync.aligned.m8n8.x4.shared.b16 {%0,%1,%2,%3}, [%4];" \
                 : "=r"(r0), "=r"(r1), "=r"(r2), "=r"(r3) : "r"(a))

#define IMMA(d, a, b) \
    asm volatile("mma.sync.aligned.m16n8k32.row.col.s32.s8.s8.s32 " \
                 "{%0,%1,%2,%3}, {%4,%5,%6,%7}, {%8,%9}, {%0,%1,%2,%3};" \
                 : "+r"((d)[0]), "+r"((d)[1]), "+r"((d)[2]), "+r"((d)[3]) \
                 : "r"((a)[0]), "r"((a)[1]), "r"((a)[2]), "r"((a)[3]), \
                   "r"((b)[0]), "r"((b)[1]))

// ---------------- Kernels ----------------

// Fused prep: absmax + zeroing, device-wide barrier, then quantize.
// 592 blocks x 256 = 4 blocks/SM (co-resident by construction -> spin barrier is safe).
__global__ __launch_bounds__(256) void simcam_prep(const float* __restrict__ x) {
    const int gtid = blockIdx.x * blockDim.x + threadIdx.x;     // 0..151551
    const int nthr = NPREP * 256;

    // ---- Phase 1: zero reductions + A-plane pad rows; partial absmax ----
    if (gtid < MDIM) { g_rpos[gtid] = 0.f; g_rneg[gtid] = 0.f; g_cpos[gtid] = 0.f; g_cneg[gtid] = 0.f; }
    if (gtid == 0) g_maxkey = 0u;
    if (gtid < 2048) {   // pad rows [5184,5248) x 256 B x 2 A-planes = 2048 uint4
        const uint4 z = make_uint4(0u, 0u, 0u, 0u);
        signed char* p = (gtid < 1024) ? g_A1 : g_A0;
        ((uint4*)(p + (size_t)MDIM * CDIM))[gtid & 1023] = z;
    }
    float ma = 0.f, mb = 0.f;
    for (int i = gtid; i < MDIM * CDIM / 4; i += nthr) {
        float4 va = ((const float4*)x)[i];
        float4 vb = ((const float4*)(x + (size_t)MDIM * CDIM))[i];
        ma = fmaxf(ma, fmaxf(fmaxf(fabsf(va.x), fabsf(va.y)), fmaxf(fabsf(va.z), fabsf(va.w))));
        mb = fmaxf(mb, fmaxf(fmaxf(fabsf(vb.x), fabsf(vb.y)), fmaxf(fabsf(vb.z), fabsf(vb.w))));
    }
    #pragma unroll
    for (int off = 16; off; off >>= 1) {
        ma = fmaxf(ma, __shfl_xor_sync(0xffffffffu, ma, off));
        mb = fmaxf(mb, __shfl_xor_sync(0xffffffffu, mb, off));
    }
    if ((threadIdx.x & 31) == 0) {
        atomicMax(&g_keyA, fkey(ma));    // idempotent across graph replays
        atomicMax(&g_keyB, fkey(mb));
    }

    // ---- Device-wide barrier (all 592 blocks co-resident) ----
    __threadfence();
    __syncthreads();
    if (threadIdx.x == 0) {
        atomicAdd(&g_ctr, 1u);
        while (atomicAdd(&g_ctr, 0u) < NPREP) { }
    }
    __syncthreads();
    __threadfence();

    // ---- Phase 2: quantize V = round(x*QMAX/absmax), split V = 128*hi + lo ----
    const float amaxA = unfkey(g_keyA), amaxB = unfkey(g_keyB);
    const float invA = (amaxA > 0.f) ? (QMAX / amaxA) : 0.f;
    const float invB = (amaxB > 0.f) ? (QMAX / amaxB) : 0.f;
    for (int id = gtid; id < 2 * MDIM * 64; id += nthr) {
        int op  = id >= MDIM * 64;
        int rid = op ? id - MDIM * 64 : id;
        float inv = op ? invB : invA;
        float4 v = ((const float4*)(x + (size_t)op * MDIM * CDIM))[rid];
        int V[4] = { (int)rintf(v.x * inv), (int)rintf(v.y * inv),
                     (int)rintf(v.z * inv), (int)rintf(v.w * inv) };
        unsigned int p1 = 0, p0 = 0;
        #pragma unroll
        for (int j = 0; j < 4; j++) {
            int hi = (V[j] + 64) >> 7;          // [-127,127]
            int lo = V[j] - (hi << 7);          // [-64,63]
            p1 |= ((unsigned)(hi & 0xFF)) << (8 * j);
            p0 |= ((unsigned)(lo & 0xFF)) << (8 * j);
        }
        ((unsigned int*)(op ? g_B1 : g_A1))[rid] = p1;
        ((unsigned int*)(op ? g_B0 : g_A0))[rid] = p0;
    }
}

// Stage load: 3072 CP16 = 12 per thread. Swizzled dst: chunk' = chunk ^ (row & 7).
__device__ __forceinline__ void load_stage(uint32_t sb, const signed char* A1s, const signed char* A0s,
                                           const signed char* B1s, const signed char* B0s,
                                           int kc, int tid) {
    #pragma unroll
    for (int i = 0; i < 12; i++) {
        int idx = tid + i * 256;                 // 0..3071
        const signed char* src;
        uint32_t off;
        int r, q;
        if (idx < 2048) {                        // A1 (0..1023), A0 (1024..2047): 128 rows x 8 chunks
            int w = idx & 1023;
            r = w >> 3; q = w & 7;
            src = (idx < 1024) ? A1s : A0s;
            off = (idx < 1024) ? OFF_A1 : OFF_A0;
        } else {                                 // B1, B0: 64 rows x 8 chunks each
            int w = idx - 2048;
            int ww = w & 511;
            r = ww >> 3; q = ww & 7;
            src = (w < 512) ? B1s : B0s;
            off = (w < 512) ? OFF_B1 : OFF_B0;
        }
        uint32_t dst = sb + off + (uint32_t)(r * 128 + ((q ^ (r & 7)) * 16));
        CP16(dst, src + (size_t)r * CDIM + kc * 128 + q * 16);
    }
}

// Fused int8 GEMM: d ~ 16384*(A1 B1) + 128*(A1 B0 + A0 B1) per 128x64 tile,
// + relu row/col sums + global max (scale cancels in final ratio).
__global__ __launch_bounds__(256, 2) void simcam_gemm() {
    extern __shared__ unsigned char dsm[];
    __shared__ float s_rp[128], s_rn[128], s_cp[64], s_cn[64], s_wmax[8];

    const int tid  = threadIdx.x;
    const int wid  = tid >> 5, lane = tid & 31;
    const int wm   = wid & 3, wn = wid >> 2;     // 4x2 warp grid; warp tile 32(M) x 32(N)
    const int bm   = blockIdx.y, bn = blockIdx.x;

    if (tid < 128) { s_rp[tid] = 0.f; s_rn[tid] = 0.f; }
    if (tid < 64)  { s_cp[tid] = 0.f; s_cn[tid] = 0.f; }

    const signed char* A1s = g_A1 + (size_t)bm * 128 * CDIM;
    const signed char* A0s = g_A0 + (size_t)bm * 128 * CDIM;
    const signed char* B1s = g_B1 + (size_t)bn * 64 * CDIM;
    const signed char* B0s = g_B0 + (size_t)bn * 64 * CDIM;
    const uint32_t dyn = smem_u32(dsm);

    // ldmatrix lane addressing (16 rows x two 16B chunk-slots, swizzled per row)
    const uint32_t arow = (uint32_t)((wm * 32 + (lane & 15)) * 128);
    const uint32_t brow = (uint32_t)((wn * 32 + (lane & 15)) * 128);
    const int      cx   = lane >> 4;             // chunk slot 0/1
    const int      swz  = lane & 7;              // row-dependent XOR key

    int acc11[2][4][4], accX[2][4][4];
    #pragma unroll
    for (int mi = 0; mi < 2; mi++)
        #pragma unroll
        for (int nf = 0; nf < 4; nf++)
            #pragma unroll
            for (int r = 0; r < 4; r++) { acc11[mi][nf][r] = 0; accX[mi][nf][r] = 0; }

    // Issue BOTH stages (whole K) up front; stage1 streams in behind stage0's compute.
    load_stage(dyn + 0 * STAGE, A1s, A0s, B1s, B0s, 0, tid);
    CP_COMMIT();
    load_stage(dyn + 1 * STAGE, A1s, A0s, B1s, B0s, 1, tid);
    CP_COMMIT();

    #pragma unroll
    for (int kc = 0; kc < 2; kc++) {
        if (kc == 0) CP_WAIT1(); else CP_WAIT0();
        __syncthreads();
        const uint32_t base = dyn + kc * STAGE;
        #pragma unroll
        for (int s = 0; s < 4; s++) {            // four k32 sub-chunks of 128 bytes
            const uint32_t ca = (uint32_t)(((2 * s + cx) ^ swz) << 4);
            uint32_t a1[2][4], a0[2][4], b1[4][2], b0[4][2];
            #pragma unroll
            for (int mi = 0; mi < 2; mi++) {
                LDSM4(a1[mi][0], a1[mi][1], a1[mi][2], a1[mi][3],
                      base + OFF_A1 + arow + mi * 2048 + ca);
                LDSM4(a0[mi][0], a0[mi][1], a0[mi][2], a0[mi][3],
                      base + OFF_A0 + arow + mi * 2048 + ca);
            }
            #pragma unroll
            for (int g = 0; g < 2; g++) {
                uint32_t r0, r1, r2, r3;
                LDSM4(r0, r1, r2, r3, base + OFF_B1 + brow + g * 2048 + ca);
                b1[2 * g][0] = r0; b1[2 * g][1] = r2;
                b1[2 * g + 1][0] = r1; b1[2 * g + 1][1] = r3;
                LDSM4(r0, r1, r2, r3, base + OFF_B0 + brow + g * 2048 + ca);
                b0[2 * g][0] = r0; b0[2 * g][1] = r2;
                b0[2 * g + 1][0] = r1; b0[2 * g + 1][1] = r3;
            }
            #pragma unroll
            for (int mi = 0; mi < 2; mi++)
                #pragma unroll
                for (int nf = 0; nf < 4; nf++) IMMA(acc11[mi][nf], a1[mi], b1[nf]);
            #pragma unroll
            for (int mi = 0; mi < 2; mi++)
                #pragma unroll
                for (int nf = 0; nf < 4; nf++) IMMA(accX[mi][nf], a1[mi], b0[nf]);
            #pragma unroll
            for (int mi = 0; mi < 2; mi++)
                #pragma unroll
                for (int nf = 0; nf < 4; nf++) IMMA(accX[mi][nf], a0[mi], b1[nf]);
        }
    }

    // ---- Fused epilogue, de-predicated ----
    // All columns valid (NBN exact). Pad rows hold exact zeros -> contribute 0 to all
    // sums; row validity is uniform per warp: invalid only when bm==NBM-1 && wm>=2.
    // rows = wm*32 + mi*16 + (lane>>2) + h*8 ; cols = wn*32 + nf*8 + (lane&3)*2 + j
    float tmax = -CUDART_INF_F;
    const bool tmax_ok = (bm < NBM - 1) || (wm < 2);

    #pragma unroll
    for (int mi = 0; mi < 2; mi++) {
        #pragma unroll
        for (int h = 0; h < 2; h++) {
            float rp = 0.f, rn = 0.f;
            #pragma unroll
            for (int nf = 0; nf < 4; nf++) {
                float v0 = (float)acc11[mi][nf][2 * h] * 16384.f + (float)accX[mi][nf][2 * h] * 128.f;
                float v1 = (float)acc11[mi][nf][2 * h + 1] * 16384.f + (float)accX[mi][nf][2 * h + 1] * 128.f;
                rp += fmaxf(v0, 0.f) + fmaxf(v1, 0.f);
                rn += fmaxf(-v0, 0.f) + fmaxf(-v1, 0.f);
                tmax = fmaxf(tmax, fmaxf(v0, v1));
            }
            rp += __shfl_xor_sync(0xffffffffu, rp, 1); rp += __shfl_xor_sync(0xffffffffu, rp, 2);
            rn += __shfl_xor_sync(0xffffffffu, rn, 1); rn += __shfl_xor_sync(0xffffffffu, rn, 2);
            if ((lane & 3) == 0) {
                int r = wm * 32 + mi * 16 + (lane >> 2) + h * 8;
                atomicAdd(&s_rp[r], rp);
                atomicAdd(&s_rn[r], rn);
            }
        }
    }
    #pragma unroll
    for (int nf = 0; nf < 4; nf++) {
        #pragma unroll
        for (int j = 0; j < 2; j++) {
            float cp = 0.f, cn = 0.f;
            #pragma unroll
            for (int mi = 0; mi < 2; mi++) {
                float v0 = (float)acc11[mi][nf][j] * 16384.f + (float)accX[mi][nf][j] * 128.f;
                float v1 = (float)acc11[mi][nf][j + 2] * 16384.f + (float)accX[mi][nf][j + 2] * 128.f;
                cp += fmaxf(v0, 0.f) + fmaxf(v1, 0.f);
                cn += fmaxf(-v0, 0.f) + fmaxf(-v1, 0.f);
            }
            cp += __shfl_xor_sync(0xffffffffu, cp, 4);
            cp += __shfl_xor_sync(0xffffffffu, cp, 8);
            cp += __shfl_xor_sync(0xffffffffu, cp, 16);
            cn += __shfl_xor_sync(0xffffffffu, cn, 4);
            cn += __shfl_xor_sync(0xffffffffu, cn, 8);
            cn += __shfl_xor_sync(0xffffffffu, cn, 16);
            if (lane < 4) {
                int c = wn * 32 + nf * 8 + lane * 2 + j;
                atomicAdd(&s_cp[c], cp);
                atomicAdd(&s_cn[c], cn);
            }
        }
    }
    if (!tmax_ok) tmax = -CUDART_INF_F;
    #pragma unroll
    for (int off = 16; off; off >>= 1)
        tmax = fmaxf(tmax, __shfl_xor_sync(0xffffffffu, tmax, off));
    if (lane == 0) s_wmax[wid] = tmax;
    __syncthreads();

    if (tid < 128) {
        int gr = bm * 128 + tid;
        if (gr < MDIM) { atomicAdd(&g_rpos[gr], s_rp[tid]); atomicAdd(&g_rneg[gr], s_rn[tid]); }
    }
    if (tid < 64) {
        atomicAdd(&g_cpos[bn * 64 + tid], s_cp[tid]);
        atomicAdd(&g_cneg[bn * 64 + tid], s_cn[tid]);
    }
    if (tid == 0) {
        float bmax = s_wmax[0];
        #pragma unroll
        for (int w = 1; w < 8; w++) bmax = fmaxf(bmax, s_wmax[w]);
        atomicMax(&g_maxkey, fkey(bmax));
    }
}

// Bilinear resize (align_corners=False) with deferred 1/|M| scale + pos/neg selection.
// Also resets the prep barrier counter for the next graph replay.
__global__ void simcam_resize(float* __restrict__ out, int total) {
    int idx = blockIdx.x * blockDim.x + threadIdx.x;
    if (idx == 0) g_ctr = 0u;
    if (idx >= total) return;
    int p   = idx / (OUT_H * OUT_W);
    int rem = idx % (OUT_H * OUT_W);
    int oy  = rem / OUT_W;
    int ox  = rem % OUT_W;

    float Mv = unfkey(g_maxkey);
    const float* src;
    float inv;
    if (Mv > 0.f)      { src = (p == 0) ? g_rpos : g_cpos; inv =  1.0f / Mv; }
    else if (Mv < 0.f) { src = (p == 0) ? g_rneg : g_cneg; inv = -1.0f / Mv; }
    else               { src = (p == 0) ? g_rpos : g_cpos; inv = 0.0f; }

    const float s = 72.0f / 224.0f;
    float ys = fmaxf(((float)oy + 0.5f) * s - 0.5f, 0.0f);
    float xs = fmaxf(((float)ox + 0.5f) * s - 0.5f, 0.0f);
    int y0 = (int)floorf(ys), x0 = (int)floorf(xs);
    int y1 = min(y0 + 1, 71), x1 = min(x0 + 1, 71);
    float wy = ys - (float)y0, wx = xs - (float)x0;

    float a = src[y0 * 72 + x0], b = src[y0 * 72 + x1];
    float c = src[y1 * 72 + x0], d = src[y1 * 72 + x1];
    out[idx] = (a * (1.f - wy) * (1.f - wx) + b * (1.f - wy) * wx
              + c * wy * (1.f - wx)         + d * wy * wx) * inv;
}

extern "C" void kernel_launch(void* const* d_in, const int* in_sizes, int n_in,
                              void* d_out, int out_size) {
    const float* x = (const float*)d_in[0];   // (2,72,72,256) fp32
    cudaFuncSetAttribute(simcam_gemm, cudaFuncAttributeMaxDynamicSharedMemorySize, DYN_SMEM);

    simcam_prep<<<NPREP, 256>>>(x);
    dim3 grid(NBN, NBM);
    simcam_gemm<<<grid, 256, DYN_SMEM>>>();
    simcam_resize<<<(out_size + 255) / 256, 256>>>((float*)d_out, out_size);
}